// round 8
// baseline (speedup 1.0000x reference)
#include <cuda_runtime.h>
#include <cuda_fp16.h>
#include <cuda_bf16.h>
#include <cstdint>

#define NN 100000
#define EE 1600000
#define HH 128
#define OUTC 40

typedef unsigned long long u64;
typedef unsigned int u32;

// ---------------- static device scratch (allocation-free rule) ----------------
__device__ __half g_h [(size_t)NN * HH];  // xW (layer1 then layer2), fp16 storage
__device__ float  g_x1[(size_t)NN * HH];  // relu(bn1(gcn1))
__device__ float  g_x2[(size_t)NN * HH];  // relu(bn2(gcn2))
__device__ float  g_dinv[NN];
__device__ int    g_deg[NN];
__device__ int    g_rowptr[NN + 1];
__device__ int    g_cursor[NN];
__device__ uint2  g_cw[EE];               // packed (col, weight-bits) per edge
__device__ int    g_bsum[128];
// bf16 hi/lo images of W1 / W2, TRANSPOSED to [N=128][K=128] so B-fragment
// k-pairs are contiguous u32 loads
__device__ __align__(16) __nv_bfloat16 g_Bh1[16384];
__device__ __align__(16) __nv_bfloat16 g_Bl1[16384];
__device__ __align__(16) __nv_bfloat16 g_Bh2[16384];
__device__ __align__(16) __nv_bfloat16 g_Bl2[16384];

// ---------------- f32x2 helpers (FFMA2 — only reachable via PTX) ----------------
__device__ __forceinline__ u64 pack2_dup(float v) {
    u64 r; asm("mov.b64 %0, {%1, %1};" : "=l"(r) : "f"(v)); return r;
}
__device__ __forceinline__ void ffma2(u64 &d, u64 a, u64 b) {
    asm("fma.rn.f32x2 %0, %1, %2, %0;" : "+l"(d) : "l"(a), "l"(b));
}

// ---------------- mma.sync bf16 (m16n8k16, fp32 accum) ----------------
__device__ __forceinline__ void mma_bf16(float* c, const u32* a, const u32* b) {
    asm volatile(
        "mma.sync.aligned.m16n8k16.row.col.f32.bf16.bf16.f32 "
        "{%0,%1,%2,%3}, {%4,%5,%6,%7}, {%8,%9}, {%0,%1,%2,%3};"
        : "+f"(c[0]), "+f"(c[1]), "+f"(c[2]), "+f"(c[3])
        : "r"(a[0]), "r"(a[1]), "r"(a[2]), "r"(a[3]), "r"(b[0]), "r"(b[1]));
}

// ---------------- CSR build ----------------
__global__ void zero_deg(int n) {
    int i = blockIdx.x * blockDim.x + threadIdx.x;
    if (i < n) g_deg[i] = 0;
}

__global__ void histo(const int* __restrict__ rows, int e) {
    int i = blockIdx.x * blockDim.x + threadIdx.x;
    if (i < e) atomicAdd(&g_deg[rows[i]], 1);
}

__global__ void scan_local(int n) {
    __shared__ int s[1024];
    int i = blockIdx.x * 1024 + threadIdx.x;
    int v = (i < n) ? g_deg[i] : 0;
    s[threadIdx.x] = v;
    __syncthreads();
    for (int off = 1; off < 1024; off <<= 1) {
        int t = (threadIdx.x >= off) ? s[threadIdx.x - off] : 0;
        __syncthreads();
        s[threadIdx.x] += t;
        __syncthreads();
    }
    if (i < n) g_rowptr[i] = s[threadIdx.x] - v;
    if (threadIdx.x == 1023) g_bsum[blockIdx.x] = s[1023];
}

__global__ void scan_sums(int nb) {
    __shared__ int s[128];
    int t = threadIdx.x;
    int v = (t < nb) ? g_bsum[t] : 0;
    s[t] = v;
    __syncthreads();
    for (int off = 1; off < 128; off <<= 1) {
        int u = (t >= off) ? s[t - off] : 0;
        __syncthreads();
        s[t] += u;
        __syncthreads();
    }
    if (t < nb) g_bsum[t] = s[t] - v;
}

__global__ void add_off(int n, int e) {
    int i = blockIdx.x * blockDim.x + threadIdx.x;
    if (i < n) {
        int v = g_rowptr[i] + g_bsum[i >> 10];
        g_rowptr[i] = v;
        g_cursor[i] = v;
        g_dinv[i]   = rsqrtf((float)g_deg[i] + 1.0f);
    }
    if (i == 0) g_rowptr[n] = e;
}

__global__ void scatter_edges(const int* __restrict__ rows, const int* __restrict__ cols, int e) {
    int i = blockIdx.x * blockDim.x + threadIdx.x;
    if (i < e) {
        int r = rows[i];
        int c = cols[i];
        int p = atomicAdd(&g_cursor[r], 1);
        g_cw[p] = make_uint2((u32)c, __float_as_uint(g_dinv[r] * g_dinv[c]));
    }
}

// ---------------- W split prep: Bt[n][k] = W[k][n] as bf16 hi/lo ----------------
__global__ void bprep(const float* __restrict__ W, int sel) {
    __nv_bfloat16* bh = sel ? g_Bh2 : g_Bh1;
    __nv_bfloat16* bl = sel ? g_Bl2 : g_Bl1;
    int i = blockIdx.x * 128 + threadIdx.x;   // 0..16383
    int k = i >> 7, n = i & 127;
    float v = W[i];                            // W[k][n] row-major
    __nv_bfloat16 h = __float2bfloat16(v);
    __nv_bfloat16 l = __float2bfloat16(v - __bfloat162float(h));
    bh[n * 128 + k] = h;
    bl[n * 128 + k] = l;
}

// ---------------- tensor GEMM: g_h[M,128](fp16) = A[M,128](fp32) @ W ----------------
// 256 threads = 8 warps; warp w covers N cols [w*16, w*16+16).
// A/B staged in smem as bf16 hi/lo, row stride 272 B (68 words -> conflict-free frags).
#define RS 272
#define SM_AH 0
#define SM_AL (SM_AH + 128 * RS)
#define SM_BH (SM_AL + 128 * RS)
#define SM_BL (SM_BH + 128 * RS)
#define SM_GT (SM_BL + 128 * RS)   // 139264 bytes total

__global__ __launch_bounds__(256) void gemm_mma(int a_sel, const float* __restrict__ Aext,
                                                int b_sel, int M) {
    extern __shared__ char sm[];
    char* sAh = sm + SM_AH;
    char* sAl = sm + SM_AL;
    char* sBh = sm + SM_BH;
    char* sBl = sm + SM_BL;

    const float* __restrict__ A  = a_sel ? g_x1 : Aext;
    const u32*   __restrict__ Bh = (const u32*)(b_sel ? g_Bh2 : g_Bh1);
    const u32*   __restrict__ Bl = (const u32*)(b_sel ? g_Bl2 : g_Bl1);

    int tid = threadIdx.x;
    int bm  = blockIdx.x * 128;

    // stage A: split fp32 -> (hi, lo) bf16 pairs
    for (int i = tid; i < 8192; i += 256) {
        int row = i >> 6, kp = i & 63;        // k = 2*kp
        int gm = bm + row; if (gm >= M) gm = M - 1;
        float2 v = *(const float2*)&A[(size_t)gm * 128 + 2 * kp];
        __nv_bfloat16 hx = __float2bfloat16(v.x);
        __nv_bfloat16 hy = __float2bfloat16(v.y);
        __nv_bfloat16 lx = __float2bfloat16(v.x - __bfloat162float(hx));
        __nv_bfloat16 ly = __float2bfloat16(v.y - __bfloat162float(hy));
        *(__nv_bfloat162*)(sAh + row * RS + kp * 4) = __halves2bfloat162(hx, hy);
        *(__nv_bfloat162*)(sAl + row * RS + kp * 4) = __halves2bfloat162(lx, ly);
    }
    // stage B (already split + transposed in global)
    for (int i = tid; i < 8192; i += 256) {
        int n = i >> 6, kp = i & 63;
        *(u32*)(sBh + n * RS + kp * 4) = Bh[n * 64 + kp];
        *(u32*)(sBl + n * RS + kp * 4) = Bl[n * 64 + kp];
    }
    __syncthreads();

    int w  = tid >> 5;
    int l  = tid & 31;
    int g  = l >> 2;          // groupID
    int b4 = l & 3;           // threadID in group
    int nbase = w * 16;

    float c[8][2][4];
#pragma unroll
    for (int mt = 0; mt < 8; mt++)
#pragma unroll
        for (int nt = 0; nt < 2; nt++)
#pragma unroll
            for (int q = 0; q < 4; q++) c[mt][nt][q] = 0.f;

    for (int kt = 0; kt < 8; kt++) {
        int koff = kt * 32 + b4 * 4;          // byte offset of k-pair in a row
        u32 bh[2][2], bl[2][2];
#pragma unroll
        for (int nt = 0; nt < 2; nt++) {
            int nrow = (nbase + nt * 8 + g) * RS + koff;
            bh[nt][0] = *(const u32*)(sBh + nrow);
            bh[nt][1] = *(const u32*)(sBh + nrow + 16);
            bl[nt][0] = *(const u32*)(sBl + nrow);
            bl[nt][1] = *(const u32*)(sBl + nrow + 16);
        }
#pragma unroll
        for (int mt = 0; mt < 8; mt++) {
            int r0 = (mt * 16 + g) * RS + koff;
            int r1 = r0 + 8 * RS;
            u32 ah[4], al[4];
            ah[0] = *(const u32*)(sAh + r0);
            ah[1] = *(const u32*)(sAh + r1);
            ah[2] = *(const u32*)(sAh + r0 + 16);
            ah[3] = *(const u32*)(sAh + r1 + 16);
            al[0] = *(const u32*)(sAl + r0);
            al[1] = *(const u32*)(sAl + r1);
            al[2] = *(const u32*)(sAl + r0 + 16);
            al[3] = *(const u32*)(sAl + r1 + 16);
#pragma unroll
            for (int nt = 0; nt < 2; nt++) {
                mma_bf16(c[mt][nt], ah, bh[nt]);
                mma_bf16(c[mt][nt], al, bh[nt]);
                mma_bf16(c[mt][nt], ah, bl[nt]);
            }
        }
    }

    // epilogue: c -> fp16 g_h
#pragma unroll
    for (int mt = 0; mt < 8; mt++) {
        int gm0 = bm + mt * 16 + g;
        int gm1 = gm0 + 8;
#pragma unroll
        for (int nt = 0; nt < 2; nt++) {
            int col = nbase + nt * 8 + b4 * 2;
            if (gm0 < M)
                *(__half2*)&g_h[(size_t)gm0 * 128 + col] = __floats2half2_rn(c[mt][nt][0], c[mt][nt][1]);
            if (gm1 < M)
                *(__half2*)&g_h[(size_t)gm1 * 128 + col] = __floats2half2_rn(c[mt][nt][2], c[mt][nt][3]);
        }
    }
}

// ---------------- gather aggregation + bias + BN + ReLU ----------------
// one HALF-WARP per destination node; each lane covers 8 fp16 channels (16B LDG)
__global__ void aggregate(const float* __restrict__ bias,
                          const float* __restrict__ gamma,
                          const float* __restrict__ beta,
                          const float* __restrict__ mean,
                          const float* __restrict__ var,
                          int dst_sel, int n) {
    int node = (blockIdx.x * blockDim.x + threadIdx.x) >> 4;
    if (node >= n) return;
    int lane = threadIdx.x & 15;
    int c0   = lane << 3;

    float di    = g_dinv[node];
    int   start = g_rowptr[node];
    int   end   = g_rowptr[node + 1];

    float acc[8];
#pragma unroll
    for (int q = 0; q < 8; q++) acc[q] = 0.f;

    int j = start;
    for (; j + 3 < end; j += 4) {
        uint2 eA = g_cw[j],     eB = g_cw[j + 1];
        uint2 eC = g_cw[j + 2], eD = g_cw[j + 3];
        float wA = __uint_as_float(eA.y), wB = __uint_as_float(eB.y);
        float wC = __uint_as_float(eC.y), wD = __uint_as_float(eD.y);
        uint4 rA = *(const uint4*)&g_h[(size_t)eA.x * 128 + c0];
        uint4 rB = *(const uint4*)&g_h[(size_t)eB.x * 128 + c0];
        uint4 rC = *(const uint4*)&g_h[(size_t)eC.x * 128 + c0];
        uint4 rD = *(const uint4*)&g_h[(size_t)eD.x * 128 + c0];
#pragma unroll
        for (int q = 0; q < 4; q++) {
            float2 fA = __half22float2(((const __half2*)&rA)[q]);
            float2 fB = __half22float2(((const __half2*)&rB)[q]);
            float2 fC = __half22float2(((const __half2*)&rC)[q]);
            float2 fD = __half22float2(((const __half2*)&rD)[q]);
            acc[2 * q]     += fA.x * wA + fB.x * wB + fC.x * wC + fD.x * wD;
            acc[2 * q + 1] += fA.y * wA + fB.y * wB + fC.y * wC + fD.y * wD;
        }
    }
    for (; j < end; j++) {
        uint2 eA = g_cw[j];
        float wA = __uint_as_float(eA.y);
        uint4 rA = *(const uint4*)&g_h[(size_t)eA.x * 128 + c0];
#pragma unroll
        for (int q = 0; q < 4; q++) {
            float2 fA = __half22float2(((const __half2*)&rA)[q]);
            acc[2 * q]     += fA.x * wA;
            acc[2 * q + 1] += fA.y * wA;
        }
    }
    {
        float ws = di * di;
        uint4 rs = *(const uint4*)&g_h[(size_t)node * 128 + c0];
#pragma unroll
        for (int q = 0; q < 4; q++) {
            float2 fs = __half22float2(((const __half2*)&rs)[q]);
            acc[2 * q]     += fs.x * ws;
            acc[2 * q + 1] += fs.y * ws;
        }
    }

    float* __restrict__ out = (dst_sel == 1) ? g_x1 : g_x2;
#pragma unroll
    for (int h = 0; h < 2; h++) {
        int c = c0 + h * 4;
        float4 bb = *(const float4*)&bias[c];
        float4 gg = *(const float4*)&gamma[c];
        float4 be = *(const float4*)&beta[c];
        float4 mm = *(const float4*)&mean[c];
        float4 vv = *(const float4*)&var[c];
        float s0 = gg.x * rsqrtf(vv.x + 1e-5f);
        float s1 = gg.y * rsqrtf(vv.y + 1e-5f);
        float s2 = gg.z * rsqrtf(vv.z + 1e-5f);
        float s3 = gg.w * rsqrtf(vv.w + 1e-5f);
        float y0 = fmaxf((acc[4 * h + 0] + bb.x - mm.x) * s0 + be.x, 0.0f);
        float y1 = fmaxf((acc[4 * h + 1] + bb.y - mm.y) * s1 + be.y, 0.0f);
        float y2 = fmaxf((acc[4 * h + 2] + bb.z - mm.z) * s2 + be.z, 0.0f);
        float y3 = fmaxf((acc[4 * h + 3] + bb.w - mm.w) * s3 + be.w, 0.0f);
        *(float4*)&out[(size_t)node * 128 + c] = make_float4(y0, y1, y2, y3);
    }
}

// ---------------- final FC: out = [x0 | x1 | x2] @ fc_W + fc_b, f32x2 inner ----------------
__global__ void fc_kernel(const float* __restrict__ x0,
                          const float* __restrict__ W,
                          const float* __restrict__ bias,
                          float* __restrict__ out, int n) {
    __shared__ float Ws[128 * 40];
    __shared__ float St[32 * 130];

    int tid = threadIdx.x;
    int r   = tid / 5;
    int cg  = (tid % 5) * 8;
    int row = blockIdx.x * 32 + r;

    u64 acc[4];
    {
        ulonglong2 b0 = *(const ulonglong2*)&bias[cg];
        ulonglong2 b1 = *(const ulonglong2*)&bias[cg + 4];
        acc[0] = b0.x; acc[1] = b0.y; acc[2] = b1.x; acc[3] = b1.y;
    }

    for (int s = 0; s < 3; s++) {
        const float* __restrict__ S = (s == 0) ? x0 : ((s == 1) ? g_x1 : g_x2);
        __syncthreads();
        for (int i = tid; i < 1280; i += 160)
            ((float4*)Ws)[i] = ((const float4*)W)[s * 1280 + i];
        for (int i = tid; i < 1024; i += 160) {
            int rr = i >> 5;
            int kk = (i & 31) << 2;
            int gr = blockIdx.x * 32 + rr;
            float4 v = (gr < n) ? *(const float4*)&S[(size_t)gr * 128 + kk]
                                : make_float4(0.f, 0.f, 0.f, 0.f);
            St[rr * 130 + kk + 0] = v.x;
            St[rr * 130 + kk + 1] = v.y;
            St[rr * 130 + kk + 2] = v.z;
            St[rr * 130 + kk + 3] = v.w;
        }
        __syncthreads();
#pragma unroll 4
        for (int k = 0; k < 128; k++) {
            u64 a2 = pack2_dup(St[r * 130 + k]);
            const float* wr = &Ws[k * 40 + cg];
            ulonglong2 w0 = *(const ulonglong2*)(wr);
            ulonglong2 w1 = *(const ulonglong2*)(wr + 4);
            ffma2(acc[0], a2, w0.x);
            ffma2(acc[1], a2, w0.y);
            ffma2(acc[2], a2, w1.x);
            ffma2(acc[3], a2, w1.y);
        }
    }
    if (row < n) {
        *(ulonglong2*)&out[(size_t)row * 40 + cg]     = make_ulonglong2(acc[0], acc[1]);
        *(ulonglong2*)&out[(size_t)row * 40 + cg + 4] = make_ulonglong2(acc[2], acc[3]);
    }
}

// ---------------- launch ----------------
extern "C" void kernel_launch(void* const* d_in, const int* in_sizes, int n_in,
                              void* d_out, int out_size) {
    const float* x   = (const float*)d_in[0];
    const int*   ei  = (const int*)  d_in[1];
    const float* W1  = (const float*)d_in[2];
    const float* b1  = (const float*)d_in[3];
    const float* W2  = (const float*)d_in[4];
    const float* b2  = (const float*)d_in[5];
    const float* g1  = (const float*)d_in[6];
    const float* be1 = (const float*)d_in[7];
    const float* m1  = (const float*)d_in[8];
    const float* v1  = (const float*)d_in[9];
    const float* g2  = (const float*)d_in[10];
    const float* be2 = (const float*)d_in[11];
    const float* m2  = (const float*)d_in[12];
    const float* v2  = (const float*)d_in[13];
    const float* fcW = (const float*)d_in[14];
    const float* fcb = (const float*)d_in[15];
    float* out = (float*)d_out;

    int N = in_sizes[0] / 128;
    int E = in_sizes[1] / 2;
    const int* rows = ei;
    const int* cols = ei + E;

    cudaFuncSetAttribute(gemm_mma, cudaFuncAttributeMaxDynamicSharedMemorySize, SM_GT);

    const int T = 256;
    int gblocks = (N + 127) / 128;
    int nb = (N + 1023) / 1024;

    bprep<<<128, 128>>>(W1, 0);                             // 0
    zero_deg<<<(N + T - 1) / T, T>>>(N);                    // 1
    histo<<<(E + T - 1) / T, T>>>(rows, E);                 // 2
    gemm_mma<<<gblocks, 256, SM_GT>>>(0, x, 0, N);          // 3 (profiled slot)
    scan_local<<<nb, 1024>>>(N);                            // 4
    bprep<<<128, 128>>>(W2, 1);                             // 5
    scan_sums<<<1, 128>>>(nb);                              // 6
    add_off<<<(N + T - 1) / T, T>>>(N, E);                  // 7
    scatter_edges<<<(E + T - 1) / T, T>>>(rows, cols, E);   // 8

    aggregate<<<(N + 15) / 16, 256>>>(b1, g1, be1, m1, v1, 1, N);
    gemm_mma<<<gblocks, 256, SM_GT>>>(1, x, 1, N);
    aggregate<<<(N + 15) / 16, 256>>>(b2, g2, be2, m2, v2, 2, N);
    fc_kernel<<<(N + 31) / 32, 160>>>(x, fcW, fcb, out, N);
}

// round 9
// speedup vs baseline: 1.1005x; 1.1005x over previous
#include <cuda_runtime.h>
#include <cuda_fp16.h>
#include <cuda_bf16.h>
#include <cstdint>

#define NN 100000
#define EE 1600000
#define HH 128
#define OUTC 40

typedef unsigned long long u64;
typedef unsigned int u32;

// ---------------- static device scratch (allocation-free rule) ----------------
__device__ __half g_h [(size_t)NN * HH];  // xW (layer1 then layer2), fp16 storage
__device__ float  g_x1[(size_t)NN * HH];  // relu(bn1(gcn1))
__device__ float  g_x2[(size_t)NN * HH];  // relu(bn2(gcn2))
__device__ float  g_dinv[NN];
__device__ int    g_deg[NN];
__device__ int    g_rowptr[NN + 1];
__device__ int    g_cursor[NN];
__device__ uint2  g_cw[EE];               // packed (col, weight-bits) per edge
__device__ int    g_bsum[128];
// FRAGMENT-MAJOR bf16 hi/lo images of W1/W2 B-operand:
// u32 index = ((w*8 + kt)*32 + lane)*4 + (nt*2 + reg), 8192 u32 = 32 KB each
__device__ __align__(16) u32 g_Bh1[8192];
__device__ __align__(16) u32 g_Bl1[8192];
__device__ __align__(16) u32 g_Bh2[8192];
__device__ __align__(16) u32 g_Bl2[8192];

// ---------------- f32x2 helpers (FFMA2 — only reachable via PTX) ----------------
__device__ __forceinline__ u64 pack2_dup(float v) {
    u64 r; asm("mov.b64 %0, {%1, %1};" : "=l"(r) : "f"(v)); return r;
}
__device__ __forceinline__ void ffma2(u64 &d, u64 a, u64 b) {
    asm("fma.rn.f32x2 %0, %1, %2, %0;" : "+l"(d) : "l"(a), "l"(b));
}

// ---------------- mma.sync bf16 (m16n8k16, fp32 accum) ----------------
__device__ __forceinline__ void mma_bf16(float* c, const u32* a, const u32* b) {
    asm volatile(
        "mma.sync.aligned.m16n8k16.row.col.f32.bf16.bf16.f32 "
        "{%0,%1,%2,%3}, {%4,%5,%6,%7}, {%8,%9}, {%0,%1,%2,%3};"
        : "+f"(c[0]), "+f"(c[1]), "+f"(c[2]), "+f"(c[3])
        : "r"(a[0]), "r"(a[1]), "r"(a[2]), "r"(a[3]), "r"(b[0]), "r"(b[1]));
}

// ---------------- CSR build ----------------
__global__ void zero_deg(int n) {
    int i = blockIdx.x * blockDim.x + threadIdx.x;
    if (i < n) g_deg[i] = 0;
}

__global__ void histo(const int* __restrict__ rows, int e) {
    int i = blockIdx.x * blockDim.x + threadIdx.x;
    if (i < e) atomicAdd(&g_deg[rows[i]], 1);
}

__global__ void scan_local(int n) {
    __shared__ int s[1024];
    int i = blockIdx.x * 1024 + threadIdx.x;
    int v = (i < n) ? g_deg[i] : 0;
    s[threadIdx.x] = v;
    __syncthreads();
    for (int off = 1; off < 1024; off <<= 1) {
        int t = (threadIdx.x >= off) ? s[threadIdx.x - off] : 0;
        __syncthreads();
        s[threadIdx.x] += t;
        __syncthreads();
    }
    if (i < n) g_rowptr[i] = s[threadIdx.x] - v;
    if (threadIdx.x == 1023) g_bsum[blockIdx.x] = s[1023];
}

__global__ void scan_sums(int nb) {
    __shared__ int s[128];
    int t = threadIdx.x;
    int v = (t < nb) ? g_bsum[t] : 0;
    s[t] = v;
    __syncthreads();
    for (int off = 1; off < 128; off <<= 1) {
        int u = (t >= off) ? s[t - off] : 0;
        __syncthreads();
        s[t] += u;
        __syncthreads();
    }
    if (t < nb) g_bsum[t] = s[t] - v;
}

__global__ void add_off(int n, int e) {
    int i = blockIdx.x * blockDim.x + threadIdx.x;
    if (i < n) {
        int v = g_rowptr[i] + g_bsum[i >> 10];
        g_rowptr[i] = v;
        g_cursor[i] = v;
        g_dinv[i]   = rsqrtf((float)g_deg[i] + 1.0f);
    }
    if (i == 0) g_rowptr[n] = e;
}

__global__ void scatter_edges(const int* __restrict__ rows, const int* __restrict__ cols, int e) {
    int i = blockIdx.x * blockDim.x + threadIdx.x;
    if (i < e) {
        int r = rows[i];
        int c = cols[i];
        int p = atomicAdd(&g_cursor[r], 1);
        g_cw[p] = make_uint2((u32)c, __float_as_uint(g_dinv[r] * g_dinv[c]));
    }
}

// ---------------- W split prep into FRAGMENT-MAJOR hi/lo bf16 images ----------------
// i iterates W row-major (k, n): coalesced read; 2-byte scatter store.
// frag element: n = w*16 + nt*8 + g, kpair = kt*8 + b4 + reg*4, halves = k parity.
__global__ void bprep(const float* __restrict__ W, int sel) {
    __nv_bfloat16* bh = (__nv_bfloat16*)(sel ? g_Bh2 : g_Bh1);
    __nv_bfloat16* bl = (__nv_bfloat16*)(sel ? g_Bl2 : g_Bl1);
    int i = blockIdx.x * 128 + threadIdx.x;   // 0..16383
    int k = i >> 7, n = i & 127;
    float v = W[i];                            // W[k][n] row-major
    __nv_bfloat16 h = __float2bfloat16(v);
    __nv_bfloat16 l = __float2bfloat16(v - __bfloat162float(h));
    int w   = n >> 4;
    int nt  = (n >> 3) & 1;
    int g   = n & 7;
    int kp  = k >> 1;
    int kt  = kp >> 3;
    int kpj = kp & 7;
    int b4  = kpj & 3;
    int reg = kpj >> 2;
    int lane = g * 4 + b4;
    int idx = (((w * 8 + kt) * 32 + lane) * 4 + nt * 2 + reg) * 2 + (k & 1);
    bh[idx] = h;
    bl[idx] = l;
}

// ---------------- tensor GEMM: g_h[M,128](fp16) = A[M,128](fp32) @ W ----------------
// 256 threads = 8 warps; warp w covers N cols [w*16, w*16+16).
// A staged fragment-major in smem (hi 32 KB + lo 32 KB); B frags LDG.128 from global.
#define SM_GT 65536

__global__ __launch_bounds__(256) void gemm_mma(int a_sel, const float* __restrict__ Aext,
                                                int b_sel, int M) {
    extern __shared__ u32 sm[];
    u32* sAh = sm;            // 8192 u32
    u32* sAl = sm + 8192;     // 8192 u32

    const float* __restrict__ A  = a_sel ? g_x1 : Aext;
    const uint4* __restrict__ B4h = (const uint4*)(b_sel ? g_Bh2 : g_Bh1);
    const uint4* __restrict__ B4l = (const uint4*)(b_sel ? g_Bl2 : g_Bl1);

    int tid = threadIdx.x;
    int bm  = blockIdx.x * 128;

    // stage A fragment-major: coalesced float2 reads, scatter bf16x2 stores
    for (int i = tid; i < 8192; i += 256) {
        int row = i >> 6, kpair = i & 63;
        int gm = bm + row; if (gm >= M) gm = M - 1;
        float2 v = *(const float2*)&A[(size_t)gm * 128 + 2 * kpair];
        __nv_bfloat16 hx = __float2bfloat16(v.x);
        __nv_bfloat16 hy = __float2bfloat16(v.y);
        __nv_bfloat16 lx = __float2bfloat16(v.x - __bfloat162float(hx));
        __nv_bfloat16 ly = __float2bfloat16(v.y - __bfloat162float(hy));
        int mt = row >> 4;
        int r  = row & 15;
        int g  = r & 7;
        int kt  = kpair >> 3;
        int kpj = kpair & 7;
        int b4  = kpj & 3;
        int reg = (r >> 3) | ((kpj >> 2) << 1);
        int lane = g * 4 + b4;
        int idx = ((mt * 8 + kt) * 32 + lane) * 4 + reg;
        __nv_bfloat162 ph = __halves2bfloat162(hx, hy);
        __nv_bfloat162 pl = __halves2bfloat162(lx, ly);
        sAh[idx] = *(u32*)&ph;
        sAl[idx] = *(u32*)&pl;
    }
    __syncthreads();

    int w = tid >> 5;
    int l = tid & 31;
    int g  = l >> 2;
    int b4 = l & 3;
    int nbase = w * 16;

    float c[8][2][4];
#pragma unroll
    for (int mt = 0; mt < 8; mt++)
#pragma unroll
        for (int nt = 0; nt < 2; nt++)
#pragma unroll
            for (int q = 0; q < 4; q++) c[mt][nt][q] = 0.f;

#pragma unroll
    for (int kt = 0; kt < 8; kt++) {
        int bidx = (w * 8 + kt) * 32 + l;
        uint4 bhv = B4h[bidx];                 // (nt0.b0, nt0.b1, nt1.b0, nt1.b1)
        uint4 blv = B4l[bidx];
        u32 bh0[2] = {bhv.x, bhv.y};
        u32 bh1[2] = {bhv.z, bhv.w};
        u32 bl0[2] = {blv.x, blv.y};
        u32 bl1[2] = {blv.z, blv.w};
#pragma unroll
        for (int mt = 0; mt < 8; mt++) {
            int aidx = ((mt * 8 + kt) * 32 + l) * 4;
            uint4 ahv = *(const uint4*)&sAh[aidx];
            uint4 alv = *(const uint4*)&sAl[aidx];
            u32 ah[4] = {ahv.x, ahv.y, ahv.z, ahv.w};
            u32 al[4] = {alv.x, alv.y, alv.z, alv.w};
            mma_bf16(c[mt][0], ah, bh0);
            mma_bf16(c[mt][0], al, bh0);
            mma_bf16(c[mt][0], ah, bl0);
            mma_bf16(c[mt][1], ah, bh1);
            mma_bf16(c[mt][1], al, bh1);
            mma_bf16(c[mt][1], ah, bl1);
        }
    }

    // epilogue: c -> fp16 g_h
#pragma unroll
    for (int mt = 0; mt < 8; mt++) {
        int gm0 = bm + mt * 16 + g;
        int gm1 = gm0 + 8;
#pragma unroll
        for (int nt = 0; nt < 2; nt++) {
            int col = nbase + nt * 8 + b4 * 2;
            if (gm0 < M)
                *(__half2*)&g_h[(size_t)gm0 * 128 + col] = __floats2half2_rn(c[mt][nt][0], c[mt][nt][1]);
            if (gm1 < M)
                *(__half2*)&g_h[(size_t)gm1 * 128 + col] = __floats2half2_rn(c[mt][nt][2], c[mt][nt][3]);
        }
    }
}

// ---------------- gather aggregation + bias + BN + ReLU ----------------
// one HALF-WARP per destination node; each lane covers 8 fp16 channels (16B LDG)
__global__ void aggregate(const float* __restrict__ bias,
                          const float* __restrict__ gamma,
                          const float* __restrict__ beta,
                          const float* __restrict__ mean,
                          const float* __restrict__ var,
                          int dst_sel, int n) {
    int node = (blockIdx.x * blockDim.x + threadIdx.x) >> 4;
    if (node >= n) return;
    int lane = threadIdx.x & 15;
    int c0   = lane << 3;

    float di    = g_dinv[node];
    int   start = g_rowptr[node];
    int   end   = g_rowptr[node + 1];

    float acc[8];
#pragma unroll
    for (int q = 0; q < 8; q++) acc[q] = 0.f;

    int j = start;
    for (; j + 3 < end; j += 4) {
        uint2 eA = g_cw[j],     eB = g_cw[j + 1];
        uint2 eC = g_cw[j + 2], eD = g_cw[j + 3];
        float wA = __uint_as_float(eA.y), wB = __uint_as_float(eB.y);
        float wC = __uint_as_float(eC.y), wD = __uint_as_float(eD.y);
        uint4 rA = *(const uint4*)&g_h[(size_t)eA.x * 128 + c0];
        uint4 rB = *(const uint4*)&g_h[(size_t)eB.x * 128 + c0];
        uint4 rC = *(const uint4*)&g_h[(size_t)eC.x * 128 + c0];
        uint4 rD = *(const uint4*)&g_h[(size_t)eD.x * 128 + c0];
#pragma unroll
        for (int q = 0; q < 4; q++) {
            float2 fA = __half22float2(((const __half2*)&rA)[q]);
            float2 fB = __half22float2(((const __half2*)&rB)[q]);
            float2 fC = __half22float2(((const __half2*)&rC)[q]);
            float2 fD = __half22float2(((const __half2*)&rD)[q]);
            acc[2 * q]     += fA.x * wA + fB.x * wB + fC.x * wC + fD.x * wD;
            acc[2 * q + 1] += fA.y * wA + fB.y * wB + fC.y * wC + fD.y * wD;
        }
    }
    for (; j < end; j++) {
        uint2 eA = g_cw[j];
        float wA = __uint_as_float(eA.y);
        uint4 rA = *(const uint4*)&g_h[(size_t)eA.x * 128 + c0];
#pragma unroll
        for (int q = 0; q < 4; q++) {
            float2 fA = __half22float2(((const __half2*)&rA)[q]);
            acc[2 * q]     += fA.x * wA;
            acc[2 * q + 1] += fA.y * wA;
        }
    }
    {
        float ws = di * di;
        uint4 rs = *(const uint4*)&g_h[(size_t)node * 128 + c0];
#pragma unroll
        for (int q = 0; q < 4; q++) {
            float2 fs = __half22float2(((const __half2*)&rs)[q]);
            acc[2 * q]     += fs.x * ws;
            acc[2 * q + 1] += fs.y * ws;
        }
    }

    float* __restrict__ out = (dst_sel == 1) ? g_x1 : g_x2;
#pragma unroll
    for (int h = 0; h < 2; h++) {
        int c = c0 + h * 4;
        float4 bb = *(const float4*)&bias[c];
        float4 gg = *(const float4*)&gamma[c];
        float4 be = *(const float4*)&beta[c];
        float4 mm = *(const float4*)&mean[c];
        float4 vv = *(const float4*)&var[c];
        float s0 = gg.x * rsqrtf(vv.x + 1e-5f);
        float s1 = gg.y * rsqrtf(vv.y + 1e-5f);
        float s2 = gg.z * rsqrtf(vv.z + 1e-5f);
        float s3 = gg.w * rsqrtf(vv.w + 1e-5f);
        float y0 = fmaxf((acc[4 * h + 0] + bb.x - mm.x) * s0 + be.x, 0.0f);
        float y1 = fmaxf((acc[4 * h + 1] + bb.y - mm.y) * s1 + be.y, 0.0f);
        float y2 = fmaxf((acc[4 * h + 2] + bb.z - mm.z) * s2 + be.z, 0.0f);
        float y3 = fmaxf((acc[4 * h + 3] + bb.w - mm.w) * s3 + be.w, 0.0f);
        *(float4*)&out[(size_t)node * 128 + c] = make_float4(y0, y1, y2, y3);
    }
}

// ---------------- final FC: out = [x0 | x1 | x2] @ fc_W + fc_b, f32x2 inner ----------------
__global__ void fc_kernel(const float* __restrict__ x0,
                          const float* __restrict__ W,
                          const float* __restrict__ bias,
                          float* __restrict__ out, int n) {
    __shared__ float Ws[128 * 40];
    __shared__ float St[32 * 130];

    int tid = threadIdx.x;
    int r   = tid / 5;
    int cg  = (tid % 5) * 8;
    int row = blockIdx.x * 32 + r;

    u64 acc[4];
    {
        ulonglong2 b0 = *(const ulonglong2*)&bias[cg];
        ulonglong2 b1 = *(const ulonglong2*)&bias[cg + 4];
        acc[0] = b0.x; acc[1] = b0.y; acc[2] = b1.x; acc[3] = b1.y;
    }

    for (int s = 0; s < 3; s++) {
        const float* __restrict__ S = (s == 0) ? x0 : ((s == 1) ? g_x1 : g_x2);
        __syncthreads();
        for (int i = tid; i < 1280; i += 160)
            ((float4*)Ws)[i] = ((const float4*)W)[s * 1280 + i];
        for (int i = tid; i < 1024; i += 160) {
            int rr = i >> 5;
            int kk = (i & 31) << 2;
            int gr = blockIdx.x * 32 + rr;
            float4 v = (gr < n) ? *(const float4*)&S[(size_t)gr * 128 + kk]
                                : make_float4(0.f, 0.f, 0.f, 0.f);
            St[rr * 130 + kk + 0] = v.x;
            St[rr * 130 + kk + 1] = v.y;
            St[rr * 130 + kk + 2] = v.z;
            St[rr * 130 + kk + 3] = v.w;
        }
        __syncthreads();
#pragma unroll 4
        for (int k = 0; k < 128; k++) {
            u64 a2 = pack2_dup(St[r * 130 + k]);
            const float* wr = &Ws[k * 40 + cg];
            ulonglong2 w0 = *(const ulonglong2*)(wr);
            ulonglong2 w1 = *(const ulonglong2*)(wr + 4);
            ffma2(acc[0], a2, w0.x);
            ffma2(acc[1], a2, w0.y);
            ffma2(acc[2], a2, w1.x);
            ffma2(acc[3], a2, w1.y);
        }
    }
    if (row < n) {
        *(ulonglong2*)&out[(size_t)row * 40 + cg]     = make_ulonglong2(acc[0], acc[1]);
        *(ulonglong2*)&out[(size_t)row * 40 + cg + 4] = make_ulonglong2(acc[2], acc[3]);
    }
}

// ---------------- launch ----------------
extern "C" void kernel_launch(void* const* d_in, const int* in_sizes, int n_in,
                              void* d_out, int out_size) {
    const float* x   = (const float*)d_in[0];
    const int*   ei  = (const int*)  d_in[1];
    const float* W1  = (const float*)d_in[2];
    const float* b1  = (const float*)d_in[3];
    const float* W2  = (const float*)d_in[4];
    const float* b2  = (const float*)d_in[5];
    const float* g1  = (const float*)d_in[6];
    const float* be1 = (const float*)d_in[7];
    const float* m1  = (const float*)d_in[8];
    const float* v1  = (const float*)d_in[9];
    const float* g2  = (const float*)d_in[10];
    const float* be2 = (const float*)d_in[11];
    const float* m2  = (const float*)d_in[12];
    const float* v2  = (const float*)d_in[13];
    const float* fcW = (const float*)d_in[14];
    const float* fcb = (const float*)d_in[15];
    float* out = (float*)d_out;

    int N = in_sizes[0] / 128;
    int E = in_sizes[1] / 2;
    const int* rows = ei;
    const int* cols = ei + E;

    cudaFuncSetAttribute(gemm_mma, cudaFuncAttributeMaxDynamicSharedMemorySize, SM_GT);

    const int T = 256;
    int gblocks = (N + 127) / 128;
    int nb = (N + 1023) / 1024;

    bprep<<<128, 128>>>(W1, 0);                             // 0
    zero_deg<<<(N + T - 1) / T, T>>>(N);                    // 1
    histo<<<(E + T - 1) / T, T>>>(rows, E);                 // 2
    gemm_mma<<<gblocks, 256, SM_GT>>>(0, x, 0, N);          // 3 (profiled slot)
    scan_local<<<nb, 1024>>>(N);                            // 4
    bprep<<<128, 128>>>(W2, 1);                             // 5
    scan_sums<<<1, 128>>>(nb);                              // 6
    add_off<<<(N + T - 1) / T, T>>>(N, E);                  // 7
    scatter_edges<<<(E + T - 1) / T, T>>>(rows, cols, E);   // 8

    aggregate<<<(N + 15) / 16, 256>>>(b1, g1, be1, m1, v1, 1, N);
    gemm_mma<<<gblocks, 256, SM_GT>>>(1, x, 1, N);
    aggregate<<<(N + 15) / 16, 256>>>(b2, g2, be2, m2, v2, 2, N);
    fc_kernel<<<(N + 31) / 32, 160>>>(x, fcW, fcb, out, N);
}

// round 10
// speedup vs baseline: 1.1193x; 1.0170x over previous
#include <cuda_runtime.h>
#include <cuda_fp16.h>
#include <cuda_bf16.h>
#include <cstdint>

#define NN 100000
#define EE 1600000
#define HH 128
#define OUTC 40

typedef unsigned long long u64;
typedef unsigned int u32;

// ---------------- static device scratch (allocation-free rule) ----------------
__device__ __half g_h [(size_t)NN * HH];  // xW (layer1 then layer2), fp16 storage
__device__ float  g_x1[(size_t)NN * HH];  // relu(bn1(gcn1))
__device__ float  g_x2[(size_t)NN * HH];  // relu(bn2(gcn2))
__device__ float  g_dinv[NN];
__device__ int    g_deg[NN];
__device__ int    g_rowptr[NN + 1];
__device__ int    g_cursor[NN];
__device__ uint2  g_cw[EE];               // packed (col, weight-bits) per edge
__device__ int    g_bsum[128];
// FRAGMENT-MAJOR bf16 hi/lo images of W1/W2 B-operand:
// u32 index = ((w*8 + kt)*32 + lane)*4 + (nt*2 + reg), 8192 u32 = 32 KB each
__device__ __align__(16) u32 g_Bh1[8192];
__device__ __align__(16) u32 g_Bl1[8192];
__device__ __align__(16) u32 g_Bh2[8192];
__device__ __align__(16) u32 g_Bl2[8192];

// ---------------- f32x2 helpers (FFMA2 — only reachable via PTX) ----------------
__device__ __forceinline__ u64 pack2_dup(float v) {
    u64 r; asm("mov.b64 %0, {%1, %1};" : "=l"(r) : "f"(v)); return r;
}
__device__ __forceinline__ void ffma2(u64 &d, u64 a, u64 b) {
    asm("fma.rn.f32x2 %0, %1, %2, %0;" : "+l"(d) : "l"(a), "l"(b));
}

// ---------------- mma.sync bf16 (m16n8k16, fp32 accum) ----------------
__device__ __forceinline__ void mma_bf16(float* c, const u32* a, const u32* b) {
    asm volatile(
        "mma.sync.aligned.m16n8k16.row.col.f32.bf16.bf16.f32 "
        "{%0,%1,%2,%3}, {%4,%5,%6,%7}, {%8,%9}, {%0,%1,%2,%3};"
        : "+f"(c[0]), "+f"(c[1]), "+f"(c[2]), "+f"(c[3])
        : "r"(a[0]), "r"(a[1]), "r"(a[2]), "r"(a[3]), "r"(b[0]), "r"(b[1]));
}

// ---------------- CSR build ----------------
__global__ void zero_deg(int n) {
    int i = blockIdx.x * blockDim.x + threadIdx.x;
    if (i < n) g_deg[i] = 0;
}

__global__ void histo(const int* __restrict__ rows, int e) {
    int i = blockIdx.x * blockDim.x + threadIdx.x;
    if (i < e) atomicAdd(&g_deg[rows[i]], 1);
}

__global__ void scan_local(int n) {
    __shared__ int s[1024];
    int i = blockIdx.x * 1024 + threadIdx.x;
    int v = (i < n) ? g_deg[i] : 0;
    s[threadIdx.x] = v;
    __syncthreads();
    for (int off = 1; off < 1024; off <<= 1) {
        int t = (threadIdx.x >= off) ? s[threadIdx.x - off] : 0;
        __syncthreads();
        s[threadIdx.x] += t;
        __syncthreads();
    }
    if (i < n) g_rowptr[i] = s[threadIdx.x] - v;
    if (threadIdx.x == 1023) g_bsum[blockIdx.x] = s[1023];
}

// add block offsets; each block redundantly scans the <=128 block sums in smem
// (scan_sums kernel fused away)
__global__ void add_off(int n, int e, int nb) {
    __shared__ int s[128];
    int t = threadIdx.x;
    if (t < 128) s[t] = (t < nb) ? g_bsum[t] : 0;
    __syncthreads();
    for (int off = 1; off < 128; off <<= 1) {
        int u = (t < 128 && t >= off) ? s[t - off] : 0;
        __syncthreads();
        if (t < 128) s[t] += u;      // inclusive scan
        __syncthreads();
    }
    int i = blockIdx.x * blockDim.x + t;
    if (i < n) {
        int blk = i >> 10;
        int off = (blk == 0) ? 0 : s[blk - 1];   // exclusive
        int v = g_rowptr[i] + off;
        g_rowptr[i] = v;
        g_cursor[i] = v;
        g_dinv[i]   = rsqrtf((float)g_deg[i] + 1.0f);
    }
    if (i == 0) g_rowptr[n] = e;
}

__global__ void scatter_edges(const int* __restrict__ rows, const int* __restrict__ cols, int e) {
    int i = blockIdx.x * blockDim.x + threadIdx.x;
    if (i < e) {
        int r = rows[i];
        int c = cols[i];
        int p = atomicAdd(&g_cursor[r], 1);
        g_cw[p] = make_uint2((u32)c, __float_as_uint(g_dinv[r] * g_dinv[c]));
    }
}

// ---------------- W split prep into FRAGMENT-MAJOR hi/lo bf16 images ----------------
__global__ void bprep(const float* __restrict__ W, int sel) {
    __nv_bfloat16* bh = (__nv_bfloat16*)(sel ? g_Bh2 : g_Bh1);
    __nv_bfloat16* bl = (__nv_bfloat16*)(sel ? g_Bl2 : g_Bl1);
    int i = blockIdx.x * 128 + threadIdx.x;   // 0..16383
    int k = i >> 7, n = i & 127;
    float v = W[i];                            // W[k][n] row-major
    __nv_bfloat16 h = __float2bfloat16(v);
    __nv_bfloat16 l = __float2bfloat16(v - __bfloat162float(h));
    int w   = n >> 4;
    int nt  = (n >> 3) & 1;
    int g   = n & 7;
    int kp  = k >> 1;
    int kt  = kp >> 3;
    int kpj = kp & 7;
    int b4  = kpj & 3;
    int reg = kpj >> 2;
    int lane = g * 4 + b4;
    int idx = (((w * 8 + kt) * 32 + lane) * 4 + nt * 2 + reg) * 2 + (k & 1);
    bh[idx] = h;
    bl[idx] = l;
}

// ---------------- tensor GEMM: g_h[M,128](fp16) = A[M,128](fp32) @ W ----------------
#define SM_GT 65536

__global__ __launch_bounds__(256) void gemm_mma(int a_sel, const float* __restrict__ Aext,
                                                int b_sel, int M) {
    extern __shared__ u32 sm[];
    u32* sAh = sm;            // 8192 u32
    u32* sAl = sm + 8192;     // 8192 u32

    const float* __restrict__ A  = a_sel ? g_x1 : Aext;
    const uint4* __restrict__ B4h = (const uint4*)(b_sel ? g_Bh2 : g_Bh1);
    const uint4* __restrict__ B4l = (const uint4*)(b_sel ? g_Bl2 : g_Bl1);

    int tid = threadIdx.x;
    int bm  = blockIdx.x * 128;

    // stage A fragment-major: coalesced float2 reads, scatter bf16x2 stores
    for (int i = tid; i < 8192; i += 256) {
        int row = i >> 6, kpair = i & 63;
        int gm = bm + row; if (gm >= M) gm = M - 1;
        float2 v = *(const float2*)&A[(size_t)gm * 128 + 2 * kpair];
        __nv_bfloat16 hx = __float2bfloat16(v.x);
        __nv_bfloat16 hy = __float2bfloat16(v.y);
        __nv_bfloat16 lx = __float2bfloat16(v.x - __bfloat162float(hx));
        __nv_bfloat16 ly = __float2bfloat16(v.y - __bfloat162float(hy));
        int mt = row >> 4;
        int r  = row & 15;
        int g  = r & 7;
        int kt  = kpair >> 3;
        int kpj = kpair & 7;
        int b4  = kpj & 3;
        int reg = (r >> 3) | ((kpj >> 2) << 1);
        int lane = g * 4 + b4;
        int idx = ((mt * 8 + kt) * 32 + lane) * 4 + reg;
        __nv_bfloat162 ph = __halves2bfloat162(hx, hy);
        __nv_bfloat162 pl = __halves2bfloat162(lx, ly);
        sAh[idx] = *(u32*)&ph;
        sAl[idx] = *(u32*)&pl;
    }
    __syncthreads();

    int w = tid >> 5;
    int l = tid & 31;
    int g  = l >> 2;
    int b4 = l & 3;
    int nbase = w * 16;

    float c[8][2][4];
#pragma unroll
    for (int mt = 0; mt < 8; mt++)
#pragma unroll
        for (int nt = 0; nt < 2; nt++)
#pragma unroll
            for (int q = 0; q < 4; q++) c[mt][nt][q] = 0.f;

#pragma unroll
    for (int kt = 0; kt < 8; kt++) {
        int bidx = (w * 8 + kt) * 32 + l;
        uint4 bhv = B4h[bidx];
        uint4 blv = B4l[bidx];
        u32 bh0[2] = {bhv.x, bhv.y};
        u32 bh1[2] = {bhv.z, bhv.w};
        u32 bl0[2] = {blv.x, blv.y};
        u32 bl1[2] = {blv.z, blv.w};
#pragma unroll
        for (int mt = 0; mt < 8; mt++) {
            int aidx = ((mt * 8 + kt) * 32 + l) * 4;
            uint4 ahv = *(const uint4*)&sAh[aidx];
            uint4 alv = *(const uint4*)&sAl[aidx];
            u32 ah[4] = {ahv.x, ahv.y, ahv.z, ahv.w};
            u32 al[4] = {alv.x, alv.y, alv.z, alv.w};
            mma_bf16(c[mt][0], ah, bh0);
            mma_bf16(c[mt][0], al, bh0);
            mma_bf16(c[mt][0], ah, bl0);
            mma_bf16(c[mt][1], ah, bh1);
            mma_bf16(c[mt][1], al, bh1);
            mma_bf16(c[mt][1], ah, bl1);
        }
    }

    // epilogue: c -> fp16 g_h
#pragma unroll
    for (int mt = 0; mt < 8; mt++) {
        int gm0 = bm + mt * 16 + g;
        int gm1 = gm0 + 8;
#pragma unroll
        for (int nt = 0; nt < 2; nt++) {
            int col = nbase + nt * 8 + b4 * 2;
            if (gm0 < M)
                *(__half2*)&g_h[(size_t)gm0 * 128 + col] = __floats2half2_rn(c[mt][nt][0], c[mt][nt][1]);
            if (gm1 < M)
                *(__half2*)&g_h[(size_t)gm1 * 128 + col] = __floats2half2_rn(c[mt][nt][2], c[mt][nt][3]);
        }
    }
}

// ---------------- gather aggregation + bias + BN + ReLU ----------------
// one HALF-WARP per destination node; lane covers 8 fp16 channels (16B LDG).
// 8-deep software pipeline: batch cw loads, then 8 independent gathers, then math.
__device__ __forceinline__ void acc_edge(float* acc, uint4 r, float w) {
#pragma unroll
    for (int q = 0; q < 4; q++) {
        float2 f = __half22float2(((const __half2*)&r)[q]);
        acc[2 * q]     += f.x * w;
        acc[2 * q + 1] += f.y * w;
    }
}

__global__ __launch_bounds__(256) void aggregate(const float* __restrict__ bias,
                          const float* __restrict__ gamma,
                          const float* __restrict__ beta,
                          const float* __restrict__ mean,
                          const float* __restrict__ var,
                          int dst_sel, int n) {
    int node = (blockIdx.x * blockDim.x + threadIdx.x) >> 4;
    if (node >= n) return;
    int lane = threadIdx.x & 15;
    int c0   = lane << 3;

    float di    = g_dinv[node];
    int   start = g_rowptr[node];
    int   end   = g_rowptr[node + 1];

    float acc[8];
#pragma unroll
    for (int q = 0; q < 8; q++) acc[q] = 0.f;

    int j = start;
    for (; j + 7 < end; j += 8) {
        uint2 e0 = g_cw[j + 0], e1 = g_cw[j + 1], e2 = g_cw[j + 2], e3 = g_cw[j + 3];
        uint2 e4 = g_cw[j + 4], e5 = g_cw[j + 5], e6 = g_cw[j + 6], e7 = g_cw[j + 7];
        uint4 r0 = *(const uint4*)&g_h[(size_t)e0.x * 128 + c0];
        uint4 r1 = *(const uint4*)&g_h[(size_t)e1.x * 128 + c0];
        uint4 r2 = *(const uint4*)&g_h[(size_t)e2.x * 128 + c0];
        uint4 r3 = *(const uint4*)&g_h[(size_t)e3.x * 128 + c0];
        uint4 r4 = *(const uint4*)&g_h[(size_t)e4.x * 128 + c0];
        uint4 r5 = *(const uint4*)&g_h[(size_t)e5.x * 128 + c0];
        uint4 r6 = *(const uint4*)&g_h[(size_t)e6.x * 128 + c0];
        uint4 r7 = *(const uint4*)&g_h[(size_t)e7.x * 128 + c0];
        acc_edge(acc, r0, __uint_as_float(e0.y));
        acc_edge(acc, r1, __uint_as_float(e1.y));
        acc_edge(acc, r2, __uint_as_float(e2.y));
        acc_edge(acc, r3, __uint_as_float(e3.y));
        acc_edge(acc, r4, __uint_as_float(e4.y));
        acc_edge(acc, r5, __uint_as_float(e5.y));
        acc_edge(acc, r6, __uint_as_float(e6.y));
        acc_edge(acc, r7, __uint_as_float(e7.y));
    }
    for (; j + 3 < end; j += 4) {
        uint2 e0 = g_cw[j + 0], e1 = g_cw[j + 1], e2 = g_cw[j + 2], e3 = g_cw[j + 3];
        uint4 r0 = *(const uint4*)&g_h[(size_t)e0.x * 128 + c0];
        uint4 r1 = *(const uint4*)&g_h[(size_t)e1.x * 128 + c0];
        uint4 r2 = *(const uint4*)&g_h[(size_t)e2.x * 128 + c0];
        uint4 r3 = *(const uint4*)&g_h[(size_t)e3.x * 128 + c0];
        acc_edge(acc, r0, __uint_as_float(e0.y));
        acc_edge(acc, r1, __uint_as_float(e1.y));
        acc_edge(acc, r2, __uint_as_float(e2.y));
        acc_edge(acc, r3, __uint_as_float(e3.y));
    }
    for (; j < end; j++) {
        uint2 e0 = g_cw[j];
        uint4 r0 = *(const uint4*)&g_h[(size_t)e0.x * 128 + c0];
        acc_edge(acc, r0, __uint_as_float(e0.y));
    }
    // self-loop
    {
        uint4 rs = *(const uint4*)&g_h[(size_t)node * 128 + c0];
        acc_edge(acc, rs, di * di);
    }

    float* __restrict__ out = (dst_sel == 1) ? g_x1 : g_x2;
#pragma unroll
    for (int h = 0; h < 2; h++) {
        int c = c0 + h * 4;
        float4 bb = *(const float4*)&bias[c];
        float4 gg = *(const float4*)&gamma[c];
        float4 be = *(const float4*)&beta[c];
        float4 mm = *(const float4*)&mean[c];
        float4 vv = *(const float4*)&var[c];
        float s0 = gg.x * rsqrtf(vv.x + 1e-5f);
        float s1 = gg.y * rsqrtf(vv.y + 1e-5f);
        float s2 = gg.z * rsqrtf(vv.z + 1e-5f);
        float s3 = gg.w * rsqrtf(vv.w + 1e-5f);
        float y0 = fmaxf((acc[4 * h + 0] + bb.x - mm.x) * s0 + be.x, 0.0f);
        float y1 = fmaxf((acc[4 * h + 1] + bb.y - mm.y) * s1 + be.y, 0.0f);
        float y2 = fmaxf((acc[4 * h + 2] + bb.z - mm.z) * s2 + be.z, 0.0f);
        float y3 = fmaxf((acc[4 * h + 3] + bb.w - mm.w) * s3 + be.w, 0.0f);
        *(float4*)&out[(size_t)node * 128 + c] = make_float4(y0, y1, y2, y3);
    }
}

// ---------------- final FC: out = [x0 | x1 | x2] @ fc_W + fc_b, f32x2 inner ----------------
__global__ void fc_kernel(const float* __restrict__ x0,
                          const float* __restrict__ W,
                          const float* __restrict__ bias,
                          float* __restrict__ out, int n) {
    __shared__ float Ws[128 * 40];
    __shared__ float St[32 * 130];

    int tid = threadIdx.x;
    int r   = tid / 5;
    int cg  = (tid % 5) * 8;
    int row = blockIdx.x * 32 + r;

    u64 acc[4];
    {
        ulonglong2 b0 = *(const ulonglong2*)&bias[cg];
        ulonglong2 b1 = *(const ulonglong2*)&bias[cg + 4];
        acc[0] = b0.x; acc[1] = b0.y; acc[2] = b1.x; acc[3] = b1.y;
    }

    for (int s = 0; s < 3; s++) {
        const float* __restrict__ S = (s == 0) ? x0 : ((s == 1) ? g_x1 : g_x2);
        __syncthreads();
        for (int i = tid; i < 1280; i += 160)
            ((float4*)Ws)[i] = ((const float4*)W)[s * 1280 + i];
        for (int i = tid; i < 1024; i += 160) {
            int rr = i >> 5;
            int kk = (i & 31) << 2;
            int gr = blockIdx.x * 32 + rr;
            float4 v = (gr < n) ? *(const float4*)&S[(size_t)gr * 128 + kk]
                                : make_float4(0.f, 0.f, 0.f, 0.f);
            St[rr * 130 + kk + 0] = v.x;
            St[rr * 130 + kk + 1] = v.y;
            St[rr * 130 + kk + 2] = v.z;
            St[rr * 130 + kk + 3] = v.w;
        }
        __syncthreads();
#pragma unroll 4
        for (int k = 0; k < 128; k++) {
            u64 a2 = pack2_dup(St[r * 130 + k]);
            const float* wr = &Ws[k * 40 + cg];
            ulonglong2 w0 = *(const ulonglong2*)(wr);
            ulonglong2 w1 = *(const ulonglong2*)(wr + 4);
            ffma2(acc[0], a2, w0.x);
            ffma2(acc[1], a2, w0.y);
            ffma2(acc[2], a2, w1.x);
            ffma2(acc[3], a2, w1.y);
        }
    }
    if (row < n) {
        *(ulonglong2*)&out[(size_t)row * 40 + cg]     = make_ulonglong2(acc[0], acc[1]);
        *(ulonglong2*)&out[(size_t)row * 40 + cg + 4] = make_ulonglong2(acc[2], acc[3]);
    }
}

// ---------------- launch ----------------
extern "C" void kernel_launch(void* const* d_in, const int* in_sizes, int n_in,
                              void* d_out, int out_size) {
    const float* x   = (const float*)d_in[0];
    const int*   ei  = (const int*)  d_in[1];
    const float* W1  = (const float*)d_in[2];
    const float* b1  = (const float*)d_in[3];
    const float* W2  = (const float*)d_in[4];
    const float* b2  = (const float*)d_in[5];
    const float* g1  = (const float*)d_in[6];
    const float* be1 = (const float*)d_in[7];
    const float* m1  = (const float*)d_in[8];
    const float* v1  = (const float*)d_in[9];
    const float* g2  = (const float*)d_in[10];
    const float* be2 = (const float*)d_in[11];
    const float* m2  = (const float*)d_in[12];
    const float* v2  = (const float*)d_in[13];
    const float* fcW = (const float*)d_in[14];
    const float* fcb = (const float*)d_in[15];
    float* out = (float*)d_out;

    int N = in_sizes[0] / 128;
    int E = in_sizes[1] / 2;
    const int* rows = ei;
    const int* cols = ei + E;

    cudaFuncSetAttribute(gemm_mma, cudaFuncAttributeMaxDynamicSharedMemorySize, SM_GT);

    const int T = 256;
    int gblocks = (N + 127) / 128;
    int nb = (N + 1023) / 1024;

    bprep<<<128, 128>>>(W1, 0);                             // 0
    zero_deg<<<(N + T - 1) / T, T>>>(N);                    // 1
    histo<<<(E + T - 1) / T, T>>>(rows, E);                 // 2
    gemm_mma<<<gblocks, 256, SM_GT>>>(0, x, 0, N);          // 3 (profiled slot)
    scan_local<<<nb, 1024>>>(N);                            // 4
    bprep<<<128, 128>>>(W2, 1);                             // 5
    add_off<<<(N + T - 1) / T, T>>>(N, E, nb);              // 6 (scan_sums fused in)
    scatter_edges<<<(E + T - 1) / T, T>>>(rows, cols, E);   // 7

    aggregate<<<(N + 15) / 16, 256>>>(b1, g1, be1, m1, v1, 1, N);
    gemm_mma<<<gblocks, 256, SM_GT>>>(1, x, 1, N);
    aggregate<<<(N + 15) / 16, 256>>>(b2, g2, be2, m2, v2, 2, N);
    fc_kernel<<<(N + 31) / 32, 160>>>(x, fcW, fcb, out, N);
}